// round 1
// baseline (speedup 1.0000x reference)
#include <cuda_runtime.h>
#include <math.h>
#include <float.h>

#define NB 4
#define NF 64
#define NPTS 8192
#define NC 11
#define NG 8
#define NPER 1024
#define ND 192            // NF*3
#define NGB 32            // NG*NB
#define KSEL 16
#define NROWS (NGB*NPER)  // 32768

// ---------------- static device scratch (no runtime allocation) ----------------
__device__ float g_Pe[NGB*NPER*ND];
__device__ float g_Pa[NGB*NPER*ND];
__device__ float g_Ve[NGB*NPER*ND];
__device__ float g_Va[NGB*NPER*ND];
__device__ float g_NPe[NGB*NPER*ND];
__device__ float g_NPa[NGB*NPER*ND];
__device__ float g_sPe[NROWS], g_sPa[NROWS], g_sNPe[NROWS], g_sNPa[NROWS];
__device__ float g_DG[(size_t)NGB*NPER*NPER];   // squared distances (raw)
__device__ float g_DN[(size_t)NGB*NPER*NPER];   // squared distances (normalized)
__device__ float g_dgsum[NROWS], g_dnsum[NROWS], g_dvsum[NROWS];
__device__ int   g_idx[NROWS*KSEL];
__device__ int   g_bg[2*NPTS];
__device__ int   g_rank[2*NPTS];

// ---------------- 1) group id per point (argmax of one-hot channels) ----------------
__global__ void bg_kernel(const float* __restrict__ E, const float* __restrict__ A) {
    int tid = blockIdx.x*blockDim.x + threadIdx.x;
    if (tid >= 2*NPTS) return;
    int side = tid / NPTS, p = tid % NPTS;
    const float* X = side ? A : E;
    // expected[0,0,p,3+c] -> offset p*NC + 3 + c
    float best = -FLT_MAX; int bi = 0;
    #pragma unroll
    for (int c = 0; c < NG; c++) {
        float v = X[(size_t)p*NC + 3 + c];
        if (v > best) { best = v; bi = c; }   // first max == jnp.argmax
    }
    g_bg[tid] = bi;
}

// ---------------- 2) stable counting sort -> rank[p] in sorted-by-group order ----------------
__global__ void rank_kernel() {
    __shared__ int cnt[16];
    int t = threadIdx.x;            // 16 threads: 2 sides x 8 groups
    int side = t / NG, g = t % NG;
    const int* bg = g_bg + side*NPTS;
    int c = 0;
    for (int p = 0; p < NPTS; p++) if (bg[p] == g) c++;
    cnt[t] = c;
    __syncthreads();
    int off = 0;
    for (int gg = 0; gg < g; gg++) off += cnt[side*NG + gg];
    int* rk = g_rank + side*NPTS;
    int k = 0;
    for (int p = 0; p < NPTS; p++)
        if (bg[p] == g) { rk[p] = off + k; k++; }   // stable within group
}

// ---------------- 3) build packed feature matrices: pos + velocity ----------------
__global__ void build_kernel(const float* __restrict__ E, const float* __restrict__ A) {
    int tid = blockIdx.x*blockDim.x + threadIdx.x;   // 2 * 4*64*8192 = 4,194,304
    int side = tid >> 21;             // 2^21 = NB*NF*NPTS
    int lin  = tid & ((1<<21)-1);
    int p = lin & (NPTS-1);
    int f = (lin >> 13) & (NF-1);
    int b = lin >> 19;
    const float* X = side ? A : E;
    size_t base = ((size_t)(b*NF + f)*NPTS + p)*NC;
    float x = X[base], y = X[base+1], z = X[base+2];
    float vx = 0.f, vy = 0.f, vz = 0.f;
    if (f > 0) {
        size_t bp = base - (size_t)NPTS*NC;
        vx = x - X[bp]; vy = y - X[bp+1]; vz = z - X[bp+2];
    }
    int rk = g_rank[side*NPTS + p];
    int g = rk >> 10, j = rk & (NPER-1);
    int gb = g*NB + b;
    size_t o = ((size_t)(gb*NPER + j))*ND + f*3;
    float* P = side ? g_Pa : g_Pe;
    float* V = side ? g_Va : g_Ve;
    P[o] = x; P[o+1] = y; P[o+2] = z;
    V[o] = vx; V[o+1] = vy; V[o+2] = vz;
}

// ---------------- 4) normalization stats + normalized features ----------------
// mean over (F,n) per coordinate d; std over (n,3) per frame f with ddof=1.
__global__ void stats_kernel() {
    int bid = blockIdx.x;                 // 64 blocks: side*32 + gb
    int side = bid >> 5, gb = bid & 31;
    const float* P = (side ? g_Pa : g_Pe) + (size_t)gb*NPER*ND;
    float*      NP = (side ? g_NPa : g_NPe) + (size_t)gb*NPER*ND;
    int t = threadIdx.x;                  // 192 threads: one column each
    int d = t % 3, f = t / 3;
    __shared__ float sarr[ND];
    __shared__ float qarr[ND];
    __shared__ float mean[3];
    __shared__ float invstd[NF];
    float s = 0.f;
    for (int j = 0; j < NPER; j++) s += P[(size_t)j*ND + t];
    sarr[t] = s;
    __syncthreads();
    if (t < 3) {
        float m = 0.f;
        for (int ff = 0; ff < NF; ff++) m += sarr[ff*3 + t];
        mean[t] = m / 65536.0f;           // NF*NPER
    }
    __syncthreads();
    float mu = mean[d];
    float s2 = 0.f, q2 = 0.f;
    for (int j = 0; j < NPER; j++) {
        float c = P[(size_t)j*ND + t] - mu;
        s2 += c; q2 += c*c;
    }
    sarr[t] = s2; qarr[t] = q2;
    __syncthreads();
    if (t < NF) {
        float S = sarr[t*3] + sarr[t*3+1] + sarr[t*3+2];
        float Q = qarr[t*3] + qarr[t*3+1] + qarr[t*3+2];
        float var = (Q - S*S/3072.0f) / 3071.0f;   // ddof=1
        invstd[t] = 1.0f / sqrtf(fmaxf(var, 1e-30f));
    }
    __syncthreads();
    float is = invstd[f];
    for (int j = 0; j < NPER; j++)
        NP[(size_t)j*ND + t] = (P[(size_t)j*ND + t] - mu) * is;
}

// ---------------- 5) row squared norms for 4 feature arrays ----------------
__global__ void sqnorm_kernel() {
    int w = (blockIdx.x*blockDim.x + threadIdx.x) >> 5;
    int lane = threadIdx.x & 31;
    if (w >= 4*NROWS) return;
    int a = w >> 15;                   // which array
    int row = w & (NROWS-1);
    const float* X = (a==0) ? g_Pe : (a==1) ? g_Pa : (a==2) ? g_NPe : g_NPa;
    float*       S = (a==0) ? g_sPe : (a==1) ? g_sPa : (a==2) ? g_sNPe : g_sNPa;
    const float* xr = X + (size_t)row*ND;
    float s = 0.f;
    #pragma unroll
    for (int t = 0; t < 6; t++) { float v = xr[t*32 + lane]; s += v*v; }
    #pragma unroll
    for (int o = 16; o; o >>= 1) s += __shfl_down_sync(0xffffffffu, s, o);
    if (!lane) S[row] = s;
}

// ---------------- 6) distance-squared matrix: tiled SGEMM (A . B^T) + norms ----------------
// grid (8, 8, 32): 128x128 tile per block over one (g,b) pair. Writes d^2 (sqrt deferred).
__global__ void __launch_bounds__(256) dist_kernel(int mode) {
    const float* A   = mode ? g_NPe  : g_Pe;
    const float* Bm  = mode ? g_NPa  : g_Pa;
    const float* sA  = mode ? g_sNPe : g_sPe;
    const float* sB  = mode ? g_sNPa : g_sPa;
    float*       D   = mode ? g_DN   : g_DG;

    int gb = blockIdx.z;
    const float* Ag = A  + (size_t)gb*NPER*ND;
    const float* Bg = Bm + (size_t)gb*NPER*ND;
    float*       Dg = D  + (size_t)gb*NPER*NPER;
    const float* sAg = sA + gb*NPER;
    const float* sBg = sB + gb*NPER;
    int row0 = blockIdx.y*128, col0 = blockIdx.x*128;

    __shared__ float As[16][128];
    __shared__ float Bs[16][128];
    int tid = threadIdx.x;
    int tx = tid & 15, ty = tid >> 4;

    float acc[8][8];
    #pragma unroll
    for (int i = 0; i < 8; i++)
        #pragma unroll
        for (int j = 0; j < 8; j++) acc[i][j] = 0.f;

    for (int kk = 0; kk < ND; kk += 16) {
        #pragma unroll
        for (int i = 0; i < 2; i++) {
            int id = tid + i*256;
            int r = id >> 2, c4 = id & 3;
            float4 va = *(const float4*)(Ag + (size_t)(row0+r)*ND + kk + c4*4);
            As[c4*4+0][r] = va.x; As[c4*4+1][r] = va.y;
            As[c4*4+2][r] = va.z; As[c4*4+3][r] = va.w;
            float4 vb = *(const float4*)(Bg + (size_t)(col0+r)*ND + kk + c4*4);
            Bs[c4*4+0][r] = vb.x; Bs[c4*4+1][r] = vb.y;
            Bs[c4*4+2][r] = vb.z; Bs[c4*4+3][r] = vb.w;
        }
        __syncthreads();
        #pragma unroll
        for (int k = 0; k < 16; k++) {
            float4 a0 = *(const float4*)&As[k][ty*4];
            float4 a1 = *(const float4*)&As[k][64 + ty*4];
            float4 b0 = *(const float4*)&Bs[k][tx*4];
            float4 b1 = *(const float4*)&Bs[k][64 + tx*4];
            float ar[8] = {a0.x,a0.y,a0.z,a0.w,a1.x,a1.y,a1.z,a1.w};
            float br[8] = {b0.x,b0.y,b0.z,b0.w,b1.x,b1.y,b1.z,b1.w};
            #pragma unroll
            for (int i = 0; i < 8; i++)
                #pragma unroll
                for (int j = 0; j < 8; j++)
                    acc[i][j] += ar[i]*br[j];
        }
        __syncthreads();
    }

    float sb[8];
    #pragma unroll
    for (int j = 0; j < 8; j++) {
        int c = col0 + ((j < 4) ? tx*4 + j : 64 + tx*4 + (j-4));
        sb[j] = sBg[c];
    }
    #pragma unroll
    for (int i = 0; i < 8; i++) {
        int r = row0 + ((i < 4) ? ty*4 + i : 64 + ty*4 + (i-4));
        float sa = sAg[r];
        float o[8];
        #pragma unroll
        for (int j = 0; j < 8; j++) o[j] = sa + sb[j] - 2.0f*acc[i][j];
        *(float4*)(Dg + (size_t)r*NPER + col0 + tx*4)      = make_float4(o[0],o[1],o[2],o[3]);
        *(float4*)(Dg + (size_t)r*NPER + col0 + 64 + tx*4) = make_float4(o[4],o[5],o[6],o[7]);
    }
}

// ---------------- 7) per-row top-16 selection (warp per row), stable tie-break ----------------
__global__ void select_kernel(int mode) {
    const float* D      = mode ? g_DN    : g_DG;
    float*       rowsum = mode ? g_dnsum : g_dgsum;
    int*         idxout = mode ? (int*)0 : g_idx;

    int w = (blockIdx.x*blockDim.x + threadIdx.x) >> 5;
    int lane = threadIdx.x & 31;
    if (w >= NROWS) return;
    const float* dr = D + (size_t)w*NPER;
    float v[32];
    #pragma unroll
    for (int t = 0; t < 32; t++) v[t] = dr[t*32 + lane];
    float sum = 0.f;
    for (int k = 0; k < KSEL; k++) {
        float bm = v[0]; int bt = 0;
        #pragma unroll
        for (int t = 1; t < 32; t++)
            if (v[t] < bm) { bm = v[t]; bt = t; }
        int bc = bt*32 + lane;
        #pragma unroll
        for (int o = 16; o; o >>= 1) {
            float om = __shfl_down_sync(0xffffffffu, bm, o);
            int   oc = __shfl_down_sync(0xffffffffu, bc, o);
            if (om < bm || (om == bm && oc < bc)) { bm = om; bc = oc; }
        }
        bc = __shfl_sync(0xffffffffu, bc, 0);
        bm = __shfl_sync(0xffffffffu, bm, 0);
        sum += sqrtf(fmaxf(bm, 1e-12f));
        if (idxout && lane == 0) idxout[w*KSEL + k] = bc;
        if ((bc & 31) == lane) {
            int t = bc >> 5;
            #pragma unroll
            for (int tt = 0; tt < 32; tt++) if (tt == t) v[tt] = FLT_MAX;
        }
    }
    if (!lane) rowsum[w] = sum;
}

// ---------------- 8) velocity distances gathered at dg's top-16 indices ----------------
__global__ void dv_kernel() {
    int w = (blockIdx.x*blockDim.x + threadIdx.x) >> 5;
    int lane = threadIdx.x & 31;
    if (w >= NROWS) return;
    int gb = w >> 10;
    const float* ve  = g_Ve + (size_t)w*ND;
    const float* vab = g_Va + ((size_t)gb << 10)*ND;
    float e[6];
    #pragma unroll
    for (int t = 0; t < 6; t++) e[t] = ve[t*32 + lane];
    float sum = 0.f;
    for (int k = 0; k < KSEL; k++) {
        int j = g_idx[w*KSEL + k];
        const float* va = vab + (size_t)j*ND;
        float s = 0.f;
        #pragma unroll
        for (int t = 0; t < 6; t++) { float d = e[t] - va[t*32 + lane]; s += d*d; }
        #pragma unroll
        for (int o = 16; o; o >>= 1) s += __shfl_xor_sync(0xffffffffu, s, o);
        sum += sqrtf(fmaxf(s, 1e-12f));
    }
    if (!lane) g_dvsum[w] = sum;
}

// ---------------- 9) deterministic final reduction ----------------
__global__ void reduce_kernel(float* __restrict__ out) {
    __shared__ float red[512];
    int t = threadIdx.x;
    for (int a = 0; a < 3; a++) {
        const float* X = (a==0) ? g_dgsum : (a==1) ? g_dnsum : g_dvsum;
        float s = 0.f;
        for (int i = t; i < NROWS; i += 512) s += X[i];
        red[t] = s;
        __syncthreads();
        for (int o = 256; o; o >>= 1) {
            if (t < o) red[t] += red[t+o];
            __syncthreads();
        }
        // mean over G*B*n*K = 524288 elements, then / sqrt(F)=8
        if (!t) out[a] = red[0] * (1.0f/(524288.0f*8.0f));
        __syncthreads();
    }
}

// ---------------- launch ----------------
extern "C" void kernel_launch(void* const* d_in, const int* in_sizes, int n_in,
                              void* d_out, int out_size) {
    const float* E = (const float*)d_in[0];
    const float* A = (const float*)d_in[1];
    float* out = (float*)d_out;

    bg_kernel<<<(2*NPTS + 255)/256, 256>>>(E, A);
    rank_kernel<<<1, 16>>>();
    build_kernel<<<(2*NB*NF*NPTS)/256, 256>>>(E, A);
    stats_kernel<<<64, 192>>>();
    sqnorm_kernel<<<(4*NROWS)/8, 256>>>();          // 8 warps/block
    dist_kernel<<<dim3(8,8,NGB), 256>>>(0);         // raw positions -> g_DG
    dist_kernel<<<dim3(8,8,NGB), 256>>>(1);         // normalized  -> g_DN
    select_kernel<<<NROWS/8, 256>>>(0);             // dg: values + indices
    select_kernel<<<NROWS/8, 256>>>(1);             // dn: values only
    dv_kernel<<<NROWS/8, 256>>>();
    reduce_kernel<<<1, 512>>>(out);
}

// round 3
// speedup vs baseline: 1.5256x; 1.5256x over previous
#include <cuda_runtime.h>
#include <math.h>
#include <float.h>

#define NB 4
#define NF 64
#define NPTS 8192
#define NC 11
#define NG 8
#define NPER 1024
#define ND 192            // NF*3
#define NGB 32            // NG*NB
#define KSEL 16
#define NROWS (NGB*NPER)  // 32768

// ---------------- static device scratch ----------------
__device__ float g_Pe[NGB*NPER*ND];
__device__ float g_Pa[NGB*NPER*ND];
__device__ float g_Ve[NGB*NPER*ND];
__device__ float g_Va[NGB*NPER*ND];
__device__ float g_NPe[NGB*NPER*ND];
__device__ float g_NPa[NGB*NPER*ND];
__device__ float g_sPe[NROWS], g_sPa[NROWS], g_sNPe[NROWS], g_sNPa[NROWS];
__device__ float g_DG[(size_t)NGB*NPER*NPER];
__device__ float g_DN[(size_t)NGB*NPER*NPER];
__device__ float g_dgsum[NROWS], g_dnsum[NROWS], g_dvsum[NROWS];
__device__ int   g_idx[NROWS*KSEL];
__device__ int   g_bg[2*NPTS];
__device__ int   g_rank[2*NPTS];

// ---------------- 1) group id per point ----------------
__global__ void bg_kernel(const float* __restrict__ E, const float* __restrict__ A) {
    int tid = blockIdx.x*blockDim.x + threadIdx.x;
    if (tid >= 2*NPTS) return;
    int side = tid / NPTS, p = tid % NPTS;
    const float* X = side ? A : E;
    float best = -FLT_MAX; int bi = 0;
    #pragma unroll
    for (int c = 0; c < NG; c++) {
        float v = X[(size_t)p*NC + 3 + c];
        if (v > best) { best = v; bi = c; }
    }
    g_bg[tid] = bi;
}

// ---------------- 2) parallel stable counting sort -> rank ----------------
__global__ void rank_kernel() {
    __shared__ int sh[NG][257];
    __shared__ int gbase[NG];
    int side = blockIdx.x;
    int t = threadIdx.x;              // 256 threads, 32 points each
    const int* bg = g_bg + side*NPTS;
    int base = t*32;
    int cnt[NG];
    #pragma unroll
    for (int g = 0; g < NG; g++) cnt[g] = 0;
    for (int i = 0; i < 32; i++) cnt[bg[base+i]]++;
    #pragma unroll
    for (int g = 0; g < NG; g++) sh[g][t] = cnt[g];
    __syncthreads();
    if (t < NG) {                      // exclusive prefix per group
        int acc = 0;
        for (int i = 0; i < 256; i++) { int c = sh[t][i]; sh[t][i] = acc; acc += c; }
        sh[t][256] = acc;
    }
    __syncthreads();
    if (t == 0) {
        int acc = 0;
        for (int g = 0; g < NG; g++) { gbase[g] = acc; acc += sh[g][256]; }
    }
    __syncthreads();
    int run[NG];
    #pragma unroll
    for (int g = 0; g < NG; g++) run[g] = gbase[g] + sh[g][t];
    int* rk = g_rank + side*NPTS;
    for (int i = 0; i < 32; i++) { int g = bg[base+i]; rk[base+i] = run[g]++; }
}

// ---------------- 3) build packed positions ----------------
__global__ void build_kernel(const float* __restrict__ E, const float* __restrict__ A) {
    int tid = blockIdx.x*blockDim.x + threadIdx.x;   // 2 * 4*64*8192
    int side = tid >> 21;
    int lin  = tid & ((1<<21)-1);
    int p = lin & (NPTS-1);
    int f = (lin >> 13) & (NF-1);
    int b = lin >> 19;
    const float* X = side ? A : E;
    size_t base = ((size_t)(b*NF + f)*NPTS + p)*NC;
    float x = X[base], y = X[base+1], z = X[base+2];
    int rk = g_rank[side*NPTS + p];
    int g = rk >> 10, j = rk & (NPER-1);
    int gb = g*NB + b;
    size_t o = ((size_t)(gb*NPER + j))*ND + f*3;
    float* P = side ? g_Pa : g_Pe;
    P[o] = x; P[o+1] = y; P[o+2] = z;
}

// ---------------- 3b) velocities from packed positions (streaming) ----------------
__global__ void vel_kernel() {
    const int TOT = NGB*NPER*ND;                     // 6,291,456
    int tid = blockIdx.x*blockDim.x + threadIdx.x;
    if (tid >= 2*TOT) return;
    int side = tid / TOT;                            // exact division (bug fix)
    int lin  = tid - side*TOT;
    const float* P = side ? g_Pa : g_Pe;
    float*       V = side ? g_Va : g_Ve;
    int col = lin % ND;                              // f*3+d
    float v = (col < 3) ? 0.0f : (P[lin] - P[lin-3]);
    V[lin] = v;
}

// ---------------- 4) fused stats + normalize ----------------
// 64 blocks (side*32+gb), 768 threads = 4 row-lanes x 192 cols.
__global__ void __launch_bounds__(768) stats_kernel() {
    int bid = blockIdx.x;
    int side = bid >> 5, gb = bid & 31;
    const float* P = (side ? g_Pa : g_Pe) + (size_t)gb*NPER*ND;
    float*      NP = (side ? g_NPa : g_NPe) + (size_t)gb*NPER*ND;
    int t = threadIdx.x % ND;         // column 0..191
    int r = threadIdx.x / ND;         // row lane 0..3
    int d = t % 3, f = t / 3;
    __shared__ float Ss[4][ND];
    __shared__ float Qs[4][ND];
    __shared__ float mean[3];
    __shared__ float invstd[NF];

    float s = 0.f, q = 0.f;
    #pragma unroll 4
    for (int j = r; j < NPER; j += 4) {
        float x = P[(size_t)j*ND + t];
        s += x; q += x*x;
    }
    Ss[r][t] = s; Qs[r][t] = q;
    __syncthreads();
    if (r == 0) {
        float S = Ss[0][t]+Ss[1][t]+Ss[2][t]+Ss[3][t];
        float Q = Qs[0][t]+Qs[1][t]+Qs[2][t]+Qs[3][t];
        Ss[0][t] = S; Qs[0][t] = Q;
    }
    __syncthreads();
    if (threadIdx.x < 3) {
        float m = 0.f;
        for (int ff = 0; ff < NF; ff++) m += Ss[0][ff*3 + threadIdx.x];
        mean[threadIdx.x] = m / 65536.0f;   // NF*NPER
    }
    __syncthreads();
    if (r == 0 && t < NF) {
        // centered sums per frame: Sc = Sx - n*mu ; Qc = Qx - 2 mu Sx + n mu^2
        float Sc = 0.f, Qc = 0.f;
        #pragma unroll
        for (int dd = 0; dd < 3; dd++) {
            float mu = mean[dd];
            float Sx = Ss[0][t*3+dd], Qx = Qs[0][t*3+dd];
            Sc += Sx - 1024.0f*mu;
            Qc += Qx - 2.0f*mu*Sx + 1024.0f*mu*mu;
        }
        float var = (Qc - Sc*Sc/3072.0f) / 3071.0f;   // ddof=1
        invstd[t] = 1.0f / sqrtf(fmaxf(var, 1e-30f));
    }
    __syncthreads();
    float mu = mean[d];
    float is = invstd[f];
    #pragma unroll 4
    for (int j = r; j < NPER; j += 4)
        NP[(size_t)j*ND + t] = (P[(size_t)j*ND + t] - mu) * is;
}

// ---------------- 5) row squared norms ----------------
__global__ void sqnorm_kernel() {
    int w = (blockIdx.x*blockDim.x + threadIdx.x) >> 5;
    int lane = threadIdx.x & 31;
    if (w >= 4*NROWS) return;
    int a = w >> 15;
    int row = w & (NROWS-1);
    const float* X = (a==0) ? g_Pe : (a==1) ? g_Pa : (a==2) ? g_NPe : g_NPa;
    float*       S = (a==0) ? g_sPe : (a==1) ? g_sPa : (a==2) ? g_sNPe : g_sNPa;
    const float* xr = X + (size_t)row*ND;
    float s = 0.f;
    #pragma unroll
    for (int t = 0; t < 6; t++) { float v = xr[t*32 + lane]; s += v*v; }
    #pragma unroll
    for (int o = 16; o; o >>= 1) s += __shfl_down_sync(0xffffffffu, s, o);
    if (!lane) S[row] = s;
}

// ---------------- 6) distance^2 matrix: double-buffered tiled SGEMM ----------------
__global__ void __launch_bounds__(256) dist_kernel(int mode) {
    const float* A   = mode ? g_NPe  : g_Pe;
    const float* Bm  = mode ? g_NPa  : g_Pa;
    const float* sA  = mode ? g_sNPe : g_sPe;
    const float* sB  = mode ? g_sNPa : g_sPa;
    float*       D   = mode ? g_DN   : g_DG;

    int gb = blockIdx.z;
    const float* Ag = A  + (size_t)gb*NPER*ND;
    const float* Bg = Bm + (size_t)gb*NPER*ND;
    float*       Dg = D  + (size_t)gb*NPER*NPER;
    const float* sAg = sA + gb*NPER;
    const float* sBg = sB + gb*NPER;
    int row0 = blockIdx.y*128, col0 = blockIdx.x*128;

    __shared__ float As[2][16][128];
    __shared__ float Bs[2][16][128];
    int tid = threadIdx.x;
    int tx = tid & 15, ty = tid >> 4;

    float acc[8][8];
    #pragma unroll
    for (int i = 0; i < 8; i++)
        #pragma unroll
        for (int j = 0; j < 8; j++) acc[i][j] = 0.f;

    float4 pa[2], pb[2];
    // prologue: load K-chunk 0
    #pragma unroll
    for (int i = 0; i < 2; i++) {
        int id = tid + i*256;
        int r = id >> 2, c4 = id & 3;
        pa[i] = *(const float4*)(Ag + (size_t)(row0+r)*ND + c4*4);
        pb[i] = *(const float4*)(Bg + (size_t)(col0+r)*ND + c4*4);
    }
    #pragma unroll
    for (int i = 0; i < 2; i++) {
        int id = tid + i*256;
        int r = id >> 2, c4 = id & 3;
        As[0][c4*4+0][r]=pa[i].x; As[0][c4*4+1][r]=pa[i].y; As[0][c4*4+2][r]=pa[i].z; As[0][c4*4+3][r]=pa[i].w;
        Bs[0][c4*4+0][r]=pb[i].x; Bs[0][c4*4+1][r]=pb[i].y; Bs[0][c4*4+2][r]=pb[i].z; Bs[0][c4*4+3][r]=pb[i].w;
    }
    __syncthreads();

    int buf = 0;
    for (int kt = 0; kt < 12; kt++) {
        if (kt < 11) {
            int kk = (kt+1)*16;
            #pragma unroll
            for (int i = 0; i < 2; i++) {
                int id = tid + i*256;
                int r = id >> 2, c4 = id & 3;
                pa[i] = *(const float4*)(Ag + (size_t)(row0+r)*ND + kk + c4*4);
                pb[i] = *(const float4*)(Bg + (size_t)(col0+r)*ND + kk + c4*4);
            }
        }
        #pragma unroll
        for (int k = 0; k < 16; k++) {
            float4 a0 = *(const float4*)&As[buf][k][ty*4];
            float4 a1 = *(const float4*)&As[buf][k][64 + ty*4];
            float4 b0 = *(const float4*)&Bs[buf][k][tx*4];
            float4 b1 = *(const float4*)&Bs[buf][k][64 + tx*4];
            float ar[8] = {a0.x,a0.y,a0.z,a0.w,a1.x,a1.y,a1.z,a1.w};
            float br[8] = {b0.x,b0.y,b0.z,b0.w,b1.x,b1.y,b1.z,b1.w};
            #pragma unroll
            for (int i = 0; i < 8; i++)
                #pragma unroll
                for (int j = 0; j < 8; j++)
                    acc[i][j] += ar[i]*br[j];
        }
        if (kt < 11) {
            int nb = buf ^ 1;
            #pragma unroll
            for (int i = 0; i < 2; i++) {
                int id = tid + i*256;
                int r = id >> 2, c4 = id & 3;
                As[nb][c4*4+0][r]=pa[i].x; As[nb][c4*4+1][r]=pa[i].y; As[nb][c4*4+2][r]=pa[i].z; As[nb][c4*4+3][r]=pa[i].w;
                Bs[nb][c4*4+0][r]=pb[i].x; Bs[nb][c4*4+1][r]=pb[i].y; Bs[nb][c4*4+2][r]=pb[i].z; Bs[nb][c4*4+3][r]=pb[i].w;
            }
            __syncthreads();
            buf = nb;
        }
    }

    float sb[8];
    #pragma unroll
    for (int j = 0; j < 8; j++) {
        int c = col0 + ((j < 4) ? tx*4 + j : 64 + tx*4 + (j-4));
        sb[j] = sBg[c];
    }
    #pragma unroll
    for (int i = 0; i < 8; i++) {
        int r = row0 + ((i < 4) ? ty*4 + i : 64 + ty*4 + (i-4));
        float sa = sAg[r];
        float o[8];
        #pragma unroll
        for (int j = 0; j < 8; j++) o[j] = sa + sb[j] - 2.0f*acc[i][j];
        *(float4*)(Dg + (size_t)r*NPER + col0 + tx*4)      = make_float4(o[0],o[1],o[2],o[3]);
        *(float4*)(Dg + (size_t)r*NPER + col0 + 64 + tx*4) = make_float4(o[4],o[5],o[6],o[7]);
    }
}

// ---------------- 7) per-row top-16 selection (warp per row) ----------------
__global__ void select_kernel(int mode) {
    const float* D      = mode ? g_DN    : g_DG;
    float*       rowsum = mode ? g_dnsum : g_dgsum;
    int*         idxout = mode ? (int*)0 : g_idx;

    int w = (blockIdx.x*blockDim.x + threadIdx.x) >> 5;
    int lane = threadIdx.x & 31;
    if (w >= NROWS) return;
    const float* dr = D + (size_t)w*NPER;
    float v[32];
    #pragma unroll
    for (int t = 0; t < 32; t++) v[t] = dr[t*32 + lane];
    float sum = 0.f;
    for (int k = 0; k < KSEL; k++) {
        float bm = v[0]; int bt = 0;
        #pragma unroll
        for (int t = 1; t < 32; t++)
            if (v[t] < bm) { bm = v[t]; bt = t; }
        int bc = bt*32 + lane;
        #pragma unroll
        for (int o = 16; o; o >>= 1) {
            float om = __shfl_down_sync(0xffffffffu, bm, o);
            int   oc = __shfl_down_sync(0xffffffffu, bc, o);
            if (om < bm || (om == bm && oc < bc)) { bm = om; bc = oc; }
        }
        bc = __shfl_sync(0xffffffffu, bc, 0);
        bm = __shfl_sync(0xffffffffu, bm, 0);
        sum += sqrtf(fmaxf(bm, 1e-12f));
        if (idxout && lane == 0) idxout[w*KSEL + k] = bc;
        if ((bc & 31) == lane) {
            int t = bc >> 5;
            #pragma unroll
            for (int tt = 0; tt < 32; tt++) if (tt == t) v[tt] = FLT_MAX;
        }
    }
    if (!lane) rowsum[w] = sum;
}

// ---------------- 8) velocity distances at dg indices ----------------
__global__ void dv_kernel() {
    int w = (blockIdx.x*blockDim.x + threadIdx.x) >> 5;
    int lane = threadIdx.x & 31;
    if (w >= NROWS) return;
    int gb = w >> 10;
    const float* ve  = g_Ve + (size_t)w*ND;
    const float* vab = g_Va + ((size_t)gb << 10)*ND;
    float e[6];
    #pragma unroll
    for (int t = 0; t < 6; t++) e[t] = ve[t*32 + lane];
    float sum = 0.f;
    for (int k = 0; k < KSEL; k++) {
        int j = g_idx[w*KSEL + k];
        const float* va = vab + (size_t)j*ND;
        float s = 0.f;
        #pragma unroll
        for (int t = 0; t < 6; t++) { float d = e[t] - va[t*32 + lane]; s += d*d; }
        #pragma unroll
        for (int o = 16; o; o >>= 1) s += __shfl_xor_sync(0xffffffffu, s, o);
        sum += sqrtf(fmaxf(s, 1e-12f));
    }
    if (!lane) g_dvsum[w] = sum;
}

// ---------------- 9) deterministic final reduction ----------------
__global__ void reduce_kernel(float* __restrict__ out) {
    __shared__ float red[512];
    int t = threadIdx.x;
    for (int a = 0; a < 3; a++) {
        const float* X = (a==0) ? g_dgsum : (a==1) ? g_dnsum : g_dvsum;
        float s = 0.f;
        for (int i = t; i < NROWS; i += 512) s += X[i];
        red[t] = s;
        __syncthreads();
        for (int o = 256; o; o >>= 1) {
            if (t < o) red[t] += red[t+o];
            __syncthreads();
        }
        if (!t) out[a] = red[0] * (1.0f/(524288.0f*8.0f));
        __syncthreads();
    }
}

// ---------------- launch ----------------
extern "C" void kernel_launch(void* const* d_in, const int* in_sizes, int n_in,
                              void* d_out, int out_size) {
    const float* E = (const float*)d_in[0];
    const float* A = (const float*)d_in[1];
    float* out = (float*)d_out;

    bg_kernel<<<(2*NPTS + 255)/256, 256>>>(E, A);
    rank_kernel<<<2, 256>>>();
    build_kernel<<<(2*NB*NF*NPTS)/256, 256>>>(E, A);
    vel_kernel<<<(2*NGB*NPER*ND + 255)/256, 256>>>();
    stats_kernel<<<64, 768>>>();
    sqnorm_kernel<<<(4*NROWS)/8, 256>>>();
    dist_kernel<<<dim3(8,8,NGB), 256>>>(0);
    dist_kernel<<<dim3(8,8,NGB), 256>>>(1);
    select_kernel<<<NROWS/8, 256>>>(0);
    select_kernel<<<NROWS/8, 256>>>(1);
    dv_kernel<<<NROWS/8, 256>>>();
    reduce_kernel<<<1, 512>>>(out);
}

// round 4
// speedup vs baseline: 2.0974x; 1.3748x over previous
#include <cuda_runtime.h>
#include <math.h>
#include <float.h>

#define NB 4
#define NF 64
#define NPTS 8192
#define NC 11
#define NG 8
#define NPER 1024
#define ND 192            // NF*3
#define NGB 32            // NG*NB
#define KSEL 16
#define NROWS (NGB*NPER)  // 32768

// ---------------- static device scratch ----------------
__device__ float g_Pe[NGB*NPER*ND];
__device__ float g_Pa[NGB*NPER*ND];
__device__ float g_Ve[NGB*NPER*ND];
__device__ float g_Va[NGB*NPER*ND];
__device__ float g_NPe[NGB*NPER*ND];
__device__ float g_NPa[NGB*NPER*ND];
__device__ float g_sPe[NROWS], g_sPa[NROWS], g_sNPe[NROWS], g_sNPa[NROWS];
__device__ float g_DG[(size_t)NGB*NPER*NPER];
__device__ float g_DN[(size_t)NGB*NPER*NPER];
__device__ float g_dgsum[NROWS], g_dnsum[NROWS], g_dvsum[NROWS];
__device__ int   g_idx[NROWS*KSEL];
__device__ int   g_bg[2*NPTS];
__device__ int   g_rank[2*NPTS];

__device__ __forceinline__ float to_tf32(float x) {
    unsigned u;
    asm("cvt.rna.tf32.f32 %0, %1;" : "=r"(u) : "f"(x));
    return __uint_as_float(u);
}

// ---------------- 1) group id per point ----------------
__global__ void bg_kernel(const float* __restrict__ E, const float* __restrict__ A) {
    int tid = blockIdx.x*blockDim.x + threadIdx.x;
    if (tid >= 2*NPTS) return;
    int side = tid / NPTS, p = tid % NPTS;
    const float* X = side ? A : E;
    float best = -FLT_MAX; int bi = 0;
    #pragma unroll
    for (int c = 0; c < NG; c++) {
        float v = X[(size_t)p*NC + 3 + c];
        if (v > best) { best = v; bi = c; }
    }
    g_bg[tid] = bi;
}

// ---------------- 2) parallel stable counting sort -> rank ----------------
__global__ void rank_kernel() {
    __shared__ int sh[NG][257];
    __shared__ int gbase[NG];
    int side = blockIdx.x;
    int t = threadIdx.x;
    const int* bg = g_bg + side*NPTS;
    int base = t*32;
    int cnt[NG];
    #pragma unroll
    for (int g = 0; g < NG; g++) cnt[g] = 0;
    for (int i = 0; i < 32; i++) cnt[bg[base+i]]++;
    #pragma unroll
    for (int g = 0; g < NG; g++) sh[g][t] = cnt[g];
    __syncthreads();
    if (t < NG) {
        int acc = 0;
        for (int i = 0; i < 256; i++) { int c = sh[t][i]; sh[t][i] = acc; acc += c; }
        sh[t][256] = acc;
    }
    __syncthreads();
    if (t == 0) {
        int acc = 0;
        for (int g = 0; g < NG; g++) { gbase[g] = acc; acc += sh[g][256]; }
    }
    __syncthreads();
    int run[NG];
    #pragma unroll
    for (int g = 0; g < NG; g++) run[g] = gbase[g] + sh[g][t];
    int* rk = g_rank + side*NPTS;
    for (int i = 0; i < 32; i++) { int g = bg[base+i]; rk[base+i] = run[g]++; }
}

// ---------------- 3) build packed positions (rounded to tf32) ----------------
__global__ void build_kernel(const float* __restrict__ E, const float* __restrict__ A) {
    int tid = blockIdx.x*blockDim.x + threadIdx.x;
    int side = tid >> 21;
    int lin  = tid & ((1<<21)-1);
    int p = lin & (NPTS-1);
    int f = (lin >> 13) & (NF-1);
    int b = lin >> 19;
    const float* X = side ? A : E;
    size_t base = ((size_t)(b*NF + f)*NPTS + p)*NC;
    float x = X[base], y = X[base+1], z = X[base+2];
    int rk = g_rank[side*NPTS + p];
    int g = rk >> 10, j = rk & (NPER-1);
    int gb = g*NB + b;
    size_t o = ((size_t)(gb*NPER + j))*ND + f*3;
    float* P = side ? g_Pa : g_Pe;
    P[o] = to_tf32(x); P[o+1] = to_tf32(y); P[o+2] = to_tf32(z);
}

// ---------------- 4) fused stats + normalize + velocity ----------------
__global__ void __launch_bounds__(768) stats_kernel() {
    int bid = blockIdx.x;
    int side = bid >> 5, gb = bid & 31;
    const float* P = (side ? g_Pa : g_Pe) + (size_t)gb*NPER*ND;
    float*      NP = (side ? g_NPa : g_NPe) + (size_t)gb*NPER*ND;
    float*       V = (side ? g_Va  : g_Ve ) + (size_t)gb*NPER*ND;
    int t = threadIdx.x % ND;
    int r = threadIdx.x / ND;
    int d = t % 3, f = t / 3;
    __shared__ float Ss[4][ND];
    __shared__ float Qs[4][ND];
    __shared__ float mean[3];
    __shared__ float invstd[NF];

    float s = 0.f, q = 0.f;
    #pragma unroll 4
    for (int j = r; j < NPER; j += 4) {
        float x = P[(size_t)j*ND + t];
        s += x; q += x*x;
    }
    Ss[r][t] = s; Qs[r][t] = q;
    __syncthreads();
    if (r == 0) {
        float S = Ss[0][t]+Ss[1][t]+Ss[2][t]+Ss[3][t];
        float Q = Qs[0][t]+Qs[1][t]+Qs[2][t]+Qs[3][t];
        Ss[0][t] = S; Qs[0][t] = Q;
    }
    __syncthreads();
    if (threadIdx.x < 3) {
        float m = 0.f;
        for (int ff = 0; ff < NF; ff++) m += Ss[0][ff*3 + threadIdx.x];
        mean[threadIdx.x] = m / 65536.0f;
    }
    __syncthreads();
    if (r == 0 && t < NF) {
        float Sc = 0.f, Qc = 0.f;
        #pragma unroll
        for (int dd = 0; dd < 3; dd++) {
            float mu = mean[dd];
            float Sx = Ss[0][t*3+dd], Qx = Qs[0][t*3+dd];
            Sc += Sx - 1024.0f*mu;
            Qc += Qx - 2.0f*mu*Sx + 1024.0f*mu*mu;
        }
        float var = (Qc - Sc*Sc/3072.0f) / 3071.0f;
        invstd[t] = 1.0f / sqrtf(fmaxf(var, 1e-30f));
    }
    __syncthreads();
    float mu = mean[d];
    float is = invstd[f];
    #pragma unroll 4
    for (int j = r; j < NPER; j += 4) {
        float x = P[(size_t)j*ND + t];
        NP[(size_t)j*ND + t] = to_tf32((x - mu) * is);
        V[(size_t)j*ND + t] = (t < 3) ? 0.0f : (x - P[(size_t)j*ND + t - 3]);
    }
}

// ---------------- 5) row squared norms ----------------
__global__ void sqnorm_kernel() {
    int w = (blockIdx.x*blockDim.x + threadIdx.x) >> 5;
    int lane = threadIdx.x & 31;
    if (w >= 4*NROWS) return;
    int a = w >> 15;
    int row = w & (NROWS-1);
    const float* X = (a==0) ? g_Pe : (a==1) ? g_Pa : (a==2) ? g_NPe : g_NPa;
    float*       S = (a==0) ? g_sPe : (a==1) ? g_sPa : (a==2) ? g_sNPe : g_sNPa;
    const float* xr = X + (size_t)row*ND;
    float s = 0.f;
    #pragma unroll
    for (int t = 0; t < 6; t++) { float v = xr[t*32 + lane]; s += v*v; }
    #pragma unroll
    for (int o = 16; o; o >>= 1) s += __shfl_down_sync(0xffffffffu, s, o);
    if (!lane) S[row] = s;
}

// ---------------- 6) distance^2 via tf32 mma.sync ----------------
#define MMA_TF32(d, a, b) \
    asm volatile("mma.sync.aligned.m16n8k8.row.col.f32.tf32.tf32.f32 " \
        "{%0,%1,%2,%3}, {%4,%5,%6,%7}, {%8,%9}, {%0,%1,%2,%3};\n" \
        : "+f"(d[0]), "+f"(d[1]), "+f"(d[2]), "+f"(d[3]) \
        : "r"(a[0]), "r"(a[1]), "r"(a[2]), "r"(a[3]), "r"(b[0]), "r"(b[1]))

#define KC 16
#define KPAD 20

__global__ void __launch_bounds__(256) dist_kernel(int mode) {
    const float* A   = mode ? g_NPe  : g_Pe;
    const float* Bm  = mode ? g_NPa  : g_Pa;
    const float* sA  = mode ? g_sNPe : g_sPe;
    const float* sB  = mode ? g_sNPa : g_sPa;
    float*       D   = mode ? g_DN   : g_DG;

    int gb = blockIdx.z;
    const float* Ag = A  + (size_t)gb*NPER*ND;
    const float* Bg = Bm + (size_t)gb*NPER*ND;
    float*       Dg = D  + (size_t)gb*NPER*NPER;
    const float* sAg = sA + gb*NPER;
    const float* sBg = sB + gb*NPER;
    int row0 = blockIdx.y*128, col0 = blockIdx.x*128;

    __shared__ float As[2][128][KPAD];
    __shared__ float Bs[2][128][KPAD];

    int tid = threadIdx.x;
    int lane = tid & 31, wid = tid >> 5;
    int wm = wid >> 2, wn = wid & 3;     // 2 x 4 warp grid
    int grp = lane >> 2, t4 = lane & 3;

    float acc[4][4][4];
    #pragma unroll
    for (int i = 0; i < 4; i++)
        #pragma unroll
        for (int j = 0; j < 4; j++)
            #pragma unroll
            for (int k = 0; k < 4; k++) acc[i][j][k] = 0.f;

    // cp.async chunk loader: chunk = 128 rows x 16 k-floats for A and B
    auto load_chunk = [&](int buf, int k0) {
        #pragma unroll
        for (int i = 0; i < 2; i++) {
            int idx = tid + i*256;
            int r = idx >> 2, kq = idx & 3;
            unsigned da = (unsigned)__cvta_generic_to_shared(&As[buf][r][kq*4]);
            const float* ga = Ag + (size_t)(row0 + r)*ND + k0 + kq*4;
            asm volatile("cp.async.ca.shared.global [%0], [%1], 16;\n" :: "r"(da), "l"(ga));
            unsigned db = (unsigned)__cvta_generic_to_shared(&Bs[buf][r][kq*4]);
            const float* gbp = Bg + (size_t)(col0 + r)*ND + k0 + kq*4;
            asm volatile("cp.async.ca.shared.global [%0], [%1], 16;\n" :: "r"(db), "l"(gbp));
        }
        asm volatile("cp.async.commit_group;\n");
    };

    load_chunk(0, 0);
    asm volatile("cp.async.wait_group 0;\n");
    __syncthreads();

    for (int c = 0; c < ND/KC; c++) {           // 12 chunks
        if (c < ND/KC - 1) load_chunk((c+1)&1, (c+1)*KC);
        int buf = c & 1;
        #pragma unroll
        for (int ks = 0; ks < 2; ks++) {
            int kb = ks*8;
            unsigned a[4][4], b[4][2];
            #pragma unroll
            for (int mf = 0; mf < 4; mf++) {
                int m = wm*64 + mf*16 + grp;
                a[mf][0] = __float_as_uint(As[buf][m    ][kb + t4]);
                a[mf][1] = __float_as_uint(As[buf][m + 8][kb + t4]);
                a[mf][2] = __float_as_uint(As[buf][m    ][kb + t4 + 4]);
                a[mf][3] = __float_as_uint(As[buf][m + 8][kb + t4 + 4]);
            }
            #pragma unroll
            for (int nf = 0; nf < 4; nf++) {
                int n = wn*32 + nf*8 + grp;
                b[nf][0] = __float_as_uint(Bs[buf][n][kb + t4]);
                b[nf][1] = __float_as_uint(Bs[buf][n][kb + t4 + 4]);
            }
            #pragma unroll
            for (int mf = 0; mf < 4; mf++)
                #pragma unroll
                for (int nf = 0; nf < 4; nf++)
                    MMA_TF32(acc[mf][nf], a[mf], b[nf]);
        }
        if (c < ND/KC - 1) {
            asm volatile("cp.async.wait_group 0;\n");
            __syncthreads();
        }
    }

    // epilogue: d^2 = |a|^2 + |b|^2 - 2ab
    #pragma unroll
    for (int mf = 0; mf < 4; mf++) {
        int rlo = row0 + wm*64 + mf*16 + grp;
        int rhi = rlo + 8;
        float salo = sAg[rlo], sahi = sAg[rhi];
        #pragma unroll
        for (int nf = 0; nf < 4; nf++) {
            int col = col0 + wn*32 + nf*8 + t4*2;
            float2 sb2 = *(const float2*)&sBg[col];
            float2 olo = make_float2(salo + sb2.x - 2.0f*acc[mf][nf][0],
                                     salo + sb2.y - 2.0f*acc[mf][nf][1]);
            float2 ohi = make_float2(sahi + sb2.x - 2.0f*acc[mf][nf][2],
                                     sahi + sb2.y - 2.0f*acc[mf][nf][3]);
            *(float2*)&Dg[(size_t)rlo*NPER + col] = olo;
            *(float2*)&Dg[(size_t)rhi*NPER + col] = ohi;
        }
    }
}

// ---------------- 7) per-row top-16 selection (warp per row) ----------------
__global__ void select_kernel(int mode) {
    const float* D      = mode ? g_DN    : g_DG;
    float*       rowsum = mode ? g_dnsum : g_dgsum;
    int*         idxout = mode ? (int*)0 : g_idx;

    int w = (blockIdx.x*blockDim.x + threadIdx.x) >> 5;
    int lane = threadIdx.x & 31;
    if (w >= NROWS) return;
    const float* dr = D + (size_t)w*NPER;
    float v[32];
    #pragma unroll
    for (int t = 0; t < 32; t++) v[t] = dr[t*32 + lane];
    float sum = 0.f;
    for (int k = 0; k < KSEL; k++) {
        float bm = v[0]; int bt = 0;
        #pragma unroll
        for (int t = 1; t < 32; t++)
            if (v[t] < bm) { bm = v[t]; bt = t; }
        int bc = bt*32 + lane;
        #pragma unroll
        for (int o = 16; o; o >>= 1) {
            float om = __shfl_down_sync(0xffffffffu, bm, o);
            int   oc = __shfl_down_sync(0xffffffffu, bc, o);
            if (om < bm || (om == bm && oc < bc)) { bm = om; bc = oc; }
        }
        bc = __shfl_sync(0xffffffffu, bc, 0);
        bm = __shfl_sync(0xffffffffu, bm, 0);
        sum += sqrtf(fmaxf(bm, 1e-12f));
        if (idxout && lane == 0) idxout[w*KSEL + k] = bc;
        if ((bc & 31) == lane) {
            int t = bc >> 5;
            #pragma unroll
            for (int tt = 0; tt < 32; tt++) if (tt == t) v[tt] = FLT_MAX;
        }
    }
    if (!lane) rowsum[w] = sum;
}

// ---------------- 8) velocity distances at dg indices ----------------
__global__ void dv_kernel() {
    int w = (blockIdx.x*blockDim.x + threadIdx.x) >> 5;
    int lane = threadIdx.x & 31;
    if (w >= NROWS) return;
    int gb = w >> 10;
    const float* ve  = g_Ve + (size_t)w*ND;
    const float* vab = g_Va + ((size_t)gb << 10)*ND;
    float e[6];
    #pragma unroll
    for (int t = 0; t < 6; t++) e[t] = ve[t*32 + lane];
    float sum = 0.f;
    for (int k = 0; k < KSEL; k++) {
        int j = g_idx[w*KSEL + k];
        const float* va = vab + (size_t)j*ND;
        float s = 0.f;
        #pragma unroll
        for (int t = 0; t < 6; t++) { float d = e[t] - va[t*32 + lane]; s += d*d; }
        #pragma unroll
        for (int o = 16; o; o >>= 1) s += __shfl_xor_sync(0xffffffffu, s, o);
        sum += sqrtf(fmaxf(s, 1e-12f));
    }
    if (!lane) g_dvsum[w] = sum;
}

// ---------------- 9) deterministic final reduction ----------------
__global__ void reduce_kernel(float* __restrict__ out) {
    __shared__ float red[512];
    int t = threadIdx.x;
    for (int a = 0; a < 3; a++) {
        const float* X = (a==0) ? g_dgsum : (a==1) ? g_dnsum : g_dvsum;
        float s = 0.f;
        for (int i = t; i < NROWS; i += 512) s += X[i];
        red[t] = s;
        __syncthreads();
        for (int o = 256; o; o >>= 1) {
            if (t < o) red[t] += red[t+o];
            __syncthreads();
        }
        if (!t) out[a] = red[0] * (1.0f/(524288.0f*8.0f));
        __syncthreads();
    }
}

// ---------------- launch ----------------
extern "C" void kernel_launch(void* const* d_in, const int* in_sizes, int n_in,
                              void* d_out, int out_size) {
    const float* E = (const float*)d_in[0];
    const float* A = (const float*)d_in[1];
    float* out = (float*)d_out;

    bg_kernel<<<(2*NPTS + 255)/256, 256>>>(E, A);
    rank_kernel<<<2, 256>>>();
    build_kernel<<<(2*NB*NF*NPTS)/256, 256>>>(E, A);
    stats_kernel<<<64, 768>>>();
    sqnorm_kernel<<<(4*NROWS)/8, 256>>>();
    dist_kernel<<<dim3(8,8,NGB), 256>>>(0);
    dist_kernel<<<dim3(8,8,NGB), 256>>>(1);
    select_kernel<<<NROWS/8, 256>>>(0);
    select_kernel<<<NROWS/8, 256>>>(1);
    dv_kernel<<<NROWS/8, 256>>>();
    reduce_kernel<<<1, 512>>>(out);
}

// round 5
// speedup vs baseline: 2.5108x; 1.1971x over previous
#include <cuda_runtime.h>
#include <math.h>
#include <float.h>

#define NB 4
#define NF 64
#define NPTS 8192
#define NC 11
#define NG 8
#define NPER 1024
#define ND 192            // NF*3
#define NGB 32            // NG*NB
#define KSEL 16
#define NROWS (NGB*NPER)  // 32768

// ---------------- static device scratch ----------------
__device__ float g_Pe[NGB*NPER*ND];
__device__ float g_Pa[NGB*NPER*ND];
__device__ float g_Ve[NGB*NPER*ND];
__device__ float g_Va[NGB*NPER*ND];
__device__ float g_NPe[NGB*NPER*ND];
__device__ float g_NPa[NGB*NPER*ND];
__device__ float g_sPe[NROWS], g_sPa[NROWS], g_sNPe[NROWS], g_sNPa[NROWS];
__device__ float g_DG[(size_t)NGB*NPER*NPER];
__device__ float g_DN[(size_t)NGB*NPER*NPER];
__device__ float g_dgsum[NROWS], g_dnsum[NROWS], g_dvsum[NROWS];
__device__ int   g_idx[NROWS*KSEL];
__device__ int   g_bg[2*NPTS];
__device__ int   g_rank[2*NPTS];
__device__ float g_partS[64*8*ND];
__device__ float g_partQ[64*8*ND];
__device__ float g_mean[64*3];
__device__ float g_inv[64*NF];

__device__ __forceinline__ float to_tf32(float x) {
    unsigned u;
    asm("cvt.rna.tf32.f32 %0, %1;" : "=r"(u) : "f"(x));
    return __uint_as_float(u);
}

// ---------------- 1) group id per point ----------------
__global__ void bg_kernel(const float* __restrict__ E, const float* __restrict__ A) {
    int tid = blockIdx.x*blockDim.x + threadIdx.x;
    if (tid >= 2*NPTS) return;
    int side = tid / NPTS, p = tid % NPTS;
    const float* X = side ? A : E;
    float best = -FLT_MAX; int bi = 0;
    #pragma unroll
    for (int c = 0; c < NG; c++) {
        float v = X[(size_t)p*NC + 3 + c];
        if (v > best) { best = v; bi = c; }
    }
    g_bg[tid] = bi;
}

// ---------------- 2) parallel stable counting sort -> rank ----------------
__global__ void rank_kernel() {
    __shared__ int sh[NG][257];
    __shared__ int gbase[NG];
    int side = blockIdx.x;
    int t = threadIdx.x;
    const int* bg = g_bg + side*NPTS;
    int base = t*32;
    int cnt[NG];
    #pragma unroll
    for (int g = 0; g < NG; g++) cnt[g] = 0;
    for (int i = 0; i < 32; i++) cnt[bg[base+i]]++;
    #pragma unroll
    for (int g = 0; g < NG; g++) sh[g][t] = cnt[g];
    __syncthreads();
    if (t < NG) {
        int acc = 0;
        for (int i = 0; i < 256; i++) { int c = sh[t][i]; sh[t][i] = acc; acc += c; }
        sh[t][256] = acc;
    }
    __syncthreads();
    if (t == 0) {
        int acc = 0;
        for (int g = 0; g < NG; g++) { gbase[g] = acc; acc += sh[g][256]; }
    }
    __syncthreads();
    int run[NG];
    #pragma unroll
    for (int g = 0; g < NG; g++) run[g] = gbase[g] + sh[g][t];
    int* rk = g_rank + side*NPTS;
    for (int i = 0; i < 32; i++) { int g = bg[base+i]; rk[base+i] = run[g]++; }
}

// ---------------- 3) build packed positions (rounded to tf32) ----------------
__global__ void build_kernel(const float* __restrict__ E, const float* __restrict__ A) {
    int tid = blockIdx.x*blockDim.x + threadIdx.x;
    int side = tid >> 21;
    int lin  = tid & ((1<<21)-1);
    int p = lin & (NPTS-1);
    int f = (lin >> 13) & (NF-1);
    int b = lin >> 19;
    const float* X = side ? A : E;
    size_t base = ((size_t)(b*NF + f)*NPTS + p)*NC;
    float x = X[base], y = X[base+1], z = X[base+2];
    int rk = g_rank[side*NPTS + p];
    int g = rk >> 10, j = rk & (NPER-1);
    int gb = g*NB + b;
    size_t o = ((size_t)(gb*NPER + j))*ND + f*3;
    float* P = side ? g_Pa : g_Pe;
    P[o] = to_tf32(x); P[o+1] = to_tf32(y); P[o+2] = to_tf32(z);
}

// ---------------- 4a) partial column sums (512 blocks) ----------------
__global__ void __launch_bounds__(768) stats_part() {
    int sgb = blockIdx.x;               // 0..63  (side*32+gb)
    int slice = blockIdx.y;             // 0..7   (128-row slice)
    int side = sgb >> 5, gb = sgb & 31;
    const float* P = (side ? g_Pa : g_Pe) + (size_t)gb*NPER*ND;
    int t = threadIdx.x % ND;
    int r = threadIdx.x / ND;
    __shared__ float Ss[4][ND];
    __shared__ float Qs[4][ND];
    float s = 0.f, q = 0.f;
    int j0 = slice*128;
    #pragma unroll 4
    for (int j = j0 + r; j < j0 + 128; j += 4) {
        float x = P[(size_t)j*ND + t];
        s += x; q += x*x;
    }
    Ss[r][t] = s; Qs[r][t] = q;
    __syncthreads();
    if (r == 0) {
        g_partS[(sgb*8 + slice)*ND + t] = Ss[0][t]+Ss[1][t]+Ss[2][t]+Ss[3][t];
        g_partQ[(sgb*8 + slice)*ND + t] = Qs[0][t]+Qs[1][t]+Qs[2][t]+Qs[3][t];
    }
}

// ---------------- 4b) finalize mean / invstd ----------------
__global__ void stats_final() {
    int sgb = blockIdx.x;               // 0..63
    int t = threadIdx.x;                // 0..191
    __shared__ float Ss[ND];
    __shared__ float Qs[ND];
    __shared__ float mean[3];
    float S = 0.f, Q = 0.f;
    #pragma unroll
    for (int sl = 0; sl < 8; sl++) {
        S += g_partS[(sgb*8 + sl)*ND + t];
        Q += g_partQ[(sgb*8 + sl)*ND + t];
    }
    Ss[t] = S; Qs[t] = Q;
    __syncthreads();
    if (t < 3) {
        float m = 0.f;
        for (int ff = 0; ff < NF; ff++) m += Ss[ff*3 + t];
        mean[t] = m / 65536.0f;
        g_mean[sgb*3 + t] = mean[t];
    }
    __syncthreads();
    if (t < NF) {
        float Sc = 0.f, Qc = 0.f;
        #pragma unroll
        for (int dd = 0; dd < 3; dd++) {
            float mu = mean[dd];
            float Sx = Ss[t*3+dd], Qx = Qs[t*3+dd];
            Sc += Sx - 1024.0f*mu;
            Qc += Qx - 2.0f*mu*Sx + 1024.0f*mu*mu;
        }
        float var = (Qc - Sc*Sc/3072.0f) / 3071.0f;   // ddof=1
        g_inv[sgb*NF + t] = 1.0f / sqrtf(fmaxf(var, 1e-30f));
    }
}

// ---------------- 4c) apply: normalize + velocity + row sqnorms (warp/row) ----------------
__global__ void __launch_bounds__(256) apply_kernel() {
    int w = blockIdx.x*8 + (threadIdx.x >> 5);   // global row 0..65535
    int lane = threadIdx.x & 31;
    int side = w >> 15;
    int sgb = w >> 10;
    int gb = sgb & 31;
    int j = w & (NPER-1);

    __shared__ float mu[3];
    __shared__ float inv[NF];
    int sgb0 = (blockIdx.x*8) >> 10;             // all 8 warps share sgb
    if (threadIdx.x < 3)  mu[threadIdx.x]  = g_mean[sgb0*3 + threadIdx.x];
    if (threadIdx.x < NF) inv[threadIdx.x] = g_inv[sgb0*NF + threadIdx.x];
    __syncthreads();

    size_t off = ((size_t)(gb*NPER + j))*ND;
    const float* P = (side ? g_Pa : g_Pe) + off;
    float* NP = (side ? g_NPa : g_NPe) + off;
    float* V  = (side ? g_Va  : g_Ve ) + off;

    float sP = 0.f, sNP = 0.f, prev = 0.f;
    #pragma unroll
    for (int i = 0; i < 6; i++) {
        int c = i*32 + lane;
        float x = P[c];
        float xm3a = __shfl_up_sync(0xffffffffu, x, 3);
        float xm3b = __shfl_sync(0xffffffffu, prev, (lane + 29) & 31);
        float xm3 = (lane >= 3) ? xm3a : xm3b;
        float v = (i == 0 && lane < 3) ? 0.f : (x - xm3);
        int d = c % 3, f = c / 3;
        float np = to_tf32((x - mu[d]) * inv[f]);
        NP[c] = np;
        V[c] = v;
        sP += x*x; sNP += np*np;
        prev = x;
    }
    #pragma unroll
    for (int o = 16; o; o >>= 1) {
        sP  += __shfl_down_sync(0xffffffffu, sP,  o);
        sNP += __shfl_down_sync(0xffffffffu, sNP, o);
    }
    if (!lane) {
        int row = w & (NROWS-1);
        (side ? g_sPa  : g_sPe )[row] = sP;
        (side ? g_sNPa : g_sNPe)[row] = sNP;
    }
}

// ---------------- 6) distance^2 via tf32 mma.sync ----------------
#define MMA_TF32(d, a, b) \
    asm volatile("mma.sync.aligned.m16n8k8.row.col.f32.tf32.tf32.f32 " \
        "{%0,%1,%2,%3}, {%4,%5,%6,%7}, {%8,%9}, {%0,%1,%2,%3};\n" \
        : "+f"(d[0]), "+f"(d[1]), "+f"(d[2]), "+f"(d[3]) \
        : "r"(a[0]), "r"(a[1]), "r"(a[2]), "r"(a[3]), "r"(b[0]), "r"(b[1]))

#define KC 16
#define KPAD 20

__global__ void __launch_bounds__(256) dist_kernel(int mode) {
    const float* A   = mode ? g_NPe  : g_Pe;
    const float* Bm  = mode ? g_NPa  : g_Pa;
    const float* sA  = mode ? g_sNPe : g_sPe;
    const float* sB  = mode ? g_sNPa : g_sPa;
    float*       D   = mode ? g_DN   : g_DG;

    int gb = blockIdx.z;
    const float* Ag = A  + (size_t)gb*NPER*ND;
    const float* Bg = Bm + (size_t)gb*NPER*ND;
    float*       Dg = D  + (size_t)gb*NPER*NPER;
    const float* sAg = sA + gb*NPER;
    const float* sBg = sB + gb*NPER;
    int row0 = blockIdx.y*128, col0 = blockIdx.x*128;

    __shared__ float As[2][128][KPAD];
    __shared__ float Bs[2][128][KPAD];

    int tid = threadIdx.x;
    int lane = tid & 31, wid = tid >> 5;
    int wm = wid >> 2, wn = wid & 3;
    int grp = lane >> 2, t4 = lane & 3;

    float acc[4][4][4];
    #pragma unroll
    for (int i = 0; i < 4; i++)
        #pragma unroll
        for (int j = 0; j < 4; j++)
            #pragma unroll
            for (int k = 0; k < 4; k++) acc[i][j][k] = 0.f;

    auto load_chunk = [&](int buf, int k0) {
        #pragma unroll
        for (int i = 0; i < 2; i++) {
            int idx = tid + i*256;
            int r = idx >> 2, kq = idx & 3;
            unsigned da = (unsigned)__cvta_generic_to_shared(&As[buf][r][kq*4]);
            const float* ga = Ag + (size_t)(row0 + r)*ND + k0 + kq*4;
            asm volatile("cp.async.ca.shared.global [%0], [%1], 16;\n" :: "r"(da), "l"(ga));
            unsigned db = (unsigned)__cvta_generic_to_shared(&Bs[buf][r][kq*4]);
            const float* gbp = Bg + (size_t)(col0 + r)*ND + k0 + kq*4;
            asm volatile("cp.async.ca.shared.global [%0], [%1], 16;\n" :: "r"(db), "l"(gbp));
        }
        asm volatile("cp.async.commit_group;\n");
    };

    load_chunk(0, 0);
    asm volatile("cp.async.wait_group 0;\n");
    __syncthreads();

    for (int c = 0; c < ND/KC; c++) {
        if (c < ND/KC - 1) load_chunk((c+1)&1, (c+1)*KC);
        int buf = c & 1;
        #pragma unroll
        for (int ks = 0; ks < 2; ks++) {
            int kb = ks*8;
            unsigned a[4][4], b[4][2];
            #pragma unroll
            for (int mf = 0; mf < 4; mf++) {
                int m = wm*64 + mf*16 + grp;
                a[mf][0] = __float_as_uint(As[buf][m    ][kb + t4]);
                a[mf][1] = __float_as_uint(As[buf][m + 8][kb + t4]);
                a[mf][2] = __float_as_uint(As[buf][m    ][kb + t4 + 4]);
                a[mf][3] = __float_as_uint(As[buf][m + 8][kb + t4 + 4]);
            }
            #pragma unroll
            for (int nf = 0; nf < 4; nf++) {
                int n = wn*32 + nf*8 + grp;
                b[nf][0] = __float_as_uint(Bs[buf][n][kb + t4]);
                b[nf][1] = __float_as_uint(Bs[buf][n][kb + t4 + 4]);
            }
            #pragma unroll
            for (int mf = 0; mf < 4; mf++)
                #pragma unroll
                for (int nf = 0; nf < 4; nf++)
                    MMA_TF32(acc[mf][nf], a[mf], b[nf]);
        }
        if (c < ND/KC - 1) {
            asm volatile("cp.async.wait_group 0;\n");
            __syncthreads();
        }
    }

    #pragma unroll
    for (int mf = 0; mf < 4; mf++) {
        int rlo = row0 + wm*64 + mf*16 + grp;
        int rhi = rlo + 8;
        float salo = sAg[rlo], sahi = sAg[rhi];
        #pragma unroll
        for (int nf = 0; nf < 4; nf++) {
            int col = col0 + wn*32 + nf*8 + t4*2;
            float2 sb2 = *(const float2*)&sBg[col];
            float2 olo = make_float2(salo + sb2.x - 2.0f*acc[mf][nf][0],
                                     salo + sb2.y - 2.0f*acc[mf][nf][1]);
            float2 ohi = make_float2(sahi + sb2.x - 2.0f*acc[mf][nf][2],
                                     sahi + sb2.y - 2.0f*acc[mf][nf][3]);
            *(float2*)&Dg[(size_t)rlo*NPER + col] = olo;
            *(float2*)&Dg[(size_t)rhi*NPER + col] = ohi;
        }
    }
}

// ---------------- 7) per-row top-16 selection (warp per row) ----------------
__global__ void select_kernel(int mode) {
    const float* D      = mode ? g_DN    : g_DG;
    float*       rowsum = mode ? g_dnsum : g_dgsum;
    int*         idxout = mode ? (int*)0 : g_idx;

    int w = (blockIdx.x*blockDim.x + threadIdx.x) >> 5;
    int lane = threadIdx.x & 31;
    if (w >= NROWS) return;
    const float* dr = D + (size_t)w*NPER;
    float v[32];
    #pragma unroll
    for (int t = 0; t < 32; t++) v[t] = dr[t*32 + lane];
    float sum = 0.f;
    for (int k = 0; k < KSEL; k++) {
        float bm = v[0]; int bt = 0;
        #pragma unroll
        for (int t = 1; t < 32; t++)
            if (v[t] < bm) { bm = v[t]; bt = t; }
        int bc = bt*32 + lane;
        #pragma unroll
        for (int o = 16; o; o >>= 1) {
            float om = __shfl_down_sync(0xffffffffu, bm, o);
            int   oc = __shfl_down_sync(0xffffffffu, bc, o);
            if (om < bm || (om == bm && oc < bc)) { bm = om; bc = oc; }
        }
        bc = __shfl_sync(0xffffffffu, bc, 0);
        bm = __shfl_sync(0xffffffffu, bm, 0);
        sum += sqrtf(fmaxf(bm, 1e-12f));
        if (idxout && lane == 0) idxout[w*KSEL + k] = bc;
        if ((bc & 31) == lane) {
            int t = bc >> 5;
            #pragma unroll
            for (int tt = 0; tt < 32; tt++) if (tt == t) v[tt] = FLT_MAX;
        }
    }
    if (!lane) rowsum[w] = sum;
}

// ---------------- 8) velocity distances at dg indices ----------------
__global__ void dv_kernel() {
    int w = (blockIdx.x*blockDim.x + threadIdx.x) >> 5;
    int lane = threadIdx.x & 31;
    if (w >= NROWS) return;
    int gb = w >> 10;
    const float* ve  = g_Ve + (size_t)w*ND;
    const float* vab = g_Va + ((size_t)gb << 10)*ND;
    float e[6];
    #pragma unroll
    for (int t = 0; t < 6; t++) e[t] = ve[t*32 + lane];
    float sum = 0.f;
    for (int k = 0; k < KSEL; k++) {
        int j = g_idx[w*KSEL + k];
        const float* va = vab + (size_t)j*ND;
        float s = 0.f;
        #pragma unroll
        for (int t = 0; t < 6; t++) { float d = e[t] - va[t*32 + lane]; s += d*d; }
        #pragma unroll
        for (int o = 16; o; o >>= 1) s += __shfl_xor_sync(0xffffffffu, s, o);
        sum += sqrtf(fmaxf(s, 1e-12f));
    }
    if (!lane) g_dvsum[w] = sum;
}

// ---------------- 9) final reduction: one block per output ----------------
__global__ void reduce_kernel(float* __restrict__ out) {
    __shared__ float red[512];
    int a = blockIdx.x;
    int t = threadIdx.x;
    const float* X = (a==0) ? g_dgsum : (a==1) ? g_dnsum : g_dvsum;
    float s = 0.f;
    for (int i = t; i < NROWS; i += 512) s += X[i];
    red[t] = s;
    __syncthreads();
    for (int o = 256; o; o >>= 1) {
        if (t < o) red[t] += red[t+o];
        __syncthreads();
    }
    if (!t) out[a] = red[0] * (1.0f/(524288.0f*8.0f));
}

// ---------------- launch ----------------
extern "C" void kernel_launch(void* const* d_in, const int* in_sizes, int n_in,
                              void* d_out, int out_size) {
    const float* E = (const float*)d_in[0];
    const float* A = (const float*)d_in[1];
    float* out = (float*)d_out;

    bg_kernel<<<(2*NPTS + 255)/256, 256>>>(E, A);
    rank_kernel<<<2, 256>>>();
    build_kernel<<<(2*NB*NF*NPTS)/256, 256>>>(E, A);
    stats_part<<<dim3(64,8), 768>>>();
    stats_final<<<64, 192>>>();
    apply_kernel<<<65536/8, 256>>>();
    dist_kernel<<<dim3(8,8,NGB), 256>>>(0);
    dist_kernel<<<dim3(8,8,NGB), 256>>>(1);
    select_kernel<<<NROWS/8, 256>>>(0);
    select_kernel<<<NROWS/8, 256>>>(1);
    dv_kernel<<<NROWS/8, 256>>>();
    reduce_kernel<<<3, 512>>>(out);
}